// round 5
// baseline (speedup 1.0000x reference)
#include <cuda_runtime.h>

// Tsit5 coefficients (fp32)
#define A21 0.161f
#define A31 (-0.008480655492356989f)
#define A32 0.335480655492357f
#define A41 2.8971530571054935f
#define A42 (-6.359448489975075f)
#define A43 4.3622954328695815f
#define A51 5.325864828439257f
#define A52 (-11.748883564062828f)
#define A53 7.4955393428898365f
#define A54 (-0.09249506636175525f)
#define A61 5.86145544294642f
#define A62 (-12.92096931784711f)
#define A63 8.159367898576159f
#define A64 (-0.071584973281401f)
#define A65 (-0.028269050394068383f)
#define B1 0.09646076681806523f
#define B2 0.01f
#define B3 0.4798896504144996f
#define B4 1.379008574103742f
#define B5 (-3.290069515436081f)
#define B6 2.324710524099774f
#define E1 (-0.001780011052225777f)
#define E2 (-0.0008164344596567469f)
#define E3 0.007880878010261995f
#define E4 (-0.1447110071732629f)
#define E5 0.5823571654525552f
#define E6 (-0.45808210592918697f)
#define E7 0.015151515151515152f

#define ATOL 1e-8f
#define RTOL 1e-4f
#define PRED_LEN 32
#define MAX_STEPS 12
#define NELEM 2

__global__ void __launch_bounds__(64) sird_kernel(
    const float* __restrict__ x,          // [B,3] beta,gamma,mu
    const float* __restrict__ gp,         // [B,1]
    const float* __restrict__ population, // [B]
    float* __restrict__ out,              // [B,32,4]
    int B)
{
    const int half = B / NELEM;
    const int tid = blockIdx.x * blockDim.x + threadIdx.x;
    if (tid >= half) return;

    int    bidx[NELEM];
    float  bN[NELEM], gm[NELEM], gamma[NELEM], mu[NELEM];
    float  S[NELEM], I[NELEM], Rr[NELEM], Dd[NELEM];
    float  dtv[NELEM], tcur[NELEM];
    float4* orow[NELEM];

#pragma unroll
    for (int e = 0; e < NELEM; ++e) {
        int b = tid + e * half;
        bidx[e] = b;
        float beta = x[3 * b + 0];
        gamma[e]   = x[3 * b + 1];
        mu[e]      = x[3 * b + 2];
        float N    = population[b];
        bN[e] = beta / N;
        gm[e] = gamma[e] + mu[e];
        S[e]  = gp[b] - 100.0f;
        I[e]  = 100.0f;
        Rr[e] = 0.0f;
        Dd[e] = 0.0f;
        dtv[e] = 0.05f;
        orow[e] = reinterpret_cast<float4*>(out + (size_t)b * (PRED_LEN * 4));
        orow[e][0] = make_float4(S[e], I[e], Rr[e], Dd[e]);
    }

    const float tstep = 32.0f / 31.0f;

    for (int iv = 0; iv < PRED_LEN - 1; ++iv) {
        const float t1 = (float)(iv + 1) * tstep;
#pragma unroll
        for (int e = 0; e < NELEM; ++e) tcur[e] = (float)iv * tstep;

        bool done[NELEM];
#pragma unroll
        for (int e = 0; e < NELEM; ++e) done[e] = false;

        for (int s = 0; s < MAX_STEPS; ++s) {
            if (done[0] && done[1]) break;

#pragma unroll
            for (int e = 0; e < NELEM; ++e) {
                const float _bN = bN[e], _gm = gm[e];
                float h = fmaxf(fminf(dtv[e], t1 - tcur[e]), 1e-9f);

#define RHS2(Sv, Iv, dS, dI)                    \
    {                                           \
        float _inf = _bN * (Sv) * (Iv);         \
        dS = -_inf;                             \
        dI = fmaf(-_gm, (Iv), _inf);            \
    }
                float k1s, k1i;
                const float I1 = I[e];
                RHS2(S[e], I[e], k1s, k1i);

                float as = fmaf(h, A21 * k1s, S[e]);
                float ai = fmaf(h, A21 * k1i, I[e]);
                const float I2 = ai;
                float k2s, k2i;
                RHS2(as, ai, k2s, k2i);

                as = fmaf(h, fmaf(A32, k2s, A31 * k1s), S[e]);
                ai = fmaf(h, fmaf(A32, k2i, A31 * k1i), I[e]);
                const float I3 = ai;
                float k3s, k3i;
                RHS2(as, ai, k3s, k3i);

                as = fmaf(h, fmaf(A43, k3s, fmaf(A42, k2s, A41 * k1s)), S[e]);
                ai = fmaf(h, fmaf(A43, k3i, fmaf(A42, k2i, A41 * k1i)), I[e]);
                const float I4 = ai;
                float k4s, k4i;
                RHS2(as, ai, k4s, k4i);

                as = fmaf(h, fmaf(A54, k4s, fmaf(A53, k3s, fmaf(A52, k2s, A51 * k1s))), S[e]);
                ai = fmaf(h, fmaf(A54, k4i, fmaf(A53, k3i, fmaf(A52, k2i, A51 * k1i))), I[e]);
                const float I5 = ai;
                float k5s, k5i;
                RHS2(as, ai, k5s, k5i);

                as = fmaf(h, fmaf(A65, k5s, fmaf(A64, k4s, fmaf(A63, k3s, fmaf(A62, k2s, A61 * k1s)))), S[e]);
                ai = fmaf(h, fmaf(A65, k5i, fmaf(A64, k4i, fmaf(A63, k3i, fmaf(A62, k2i, A61 * k1i)))), I[e]);
                const float I6 = ai;
                float k6s, k6i;
                RHS2(as, ai, k6s, k6i);

                float nS = fmaf(h, fmaf(B6, k6s, fmaf(B5, k5s, fmaf(B4, k4s, fmaf(B3, k3s, fmaf(B2, k2s, B1 * k1s))))), S[e]);
                float nI = fmaf(h, fmaf(B6, k6i, fmaf(B5, k5i, fmaf(B4, k4i, fmaf(B3, k3i, fmaf(B2, k2i, B1 * k1i))))), I[e]);
                const float I7 = nI;

                // R/D via factored I-stage sums
                const float SB = fmaf(B6, I6, fmaf(B5, I5, fmaf(B4, I4, fmaf(B3, I3, fmaf(B2, I2, B1 * I1)))));
                const float hg = h * gamma[e];
                const float hm = h * mu[e];
                float nR = fmaf(hg, SB, Rr[e]);
                float nD = fmaf(hm, SB, Dd[e]);

                float k7s, k7i;
                RHS2(nS, nI, k7s, k7i);
#undef RHS2

                float es = h * fmaf(E7, k7s, fmaf(E6, k6s, fmaf(E5, k5s, fmaf(E4, k4s, fmaf(E3, k3s, fmaf(E2, k2s, E1 * k1s))))));
                float ei = h * fmaf(E7, k7i, fmaf(E6, k6i, fmaf(E5, k5i, fmaf(E4, k4i, fmaf(E3, k3i, fmaf(E2, k2i, E1 * k1i))))));
                const float SE = fmaf(E7, I7, fmaf(E6, I6, fmaf(E5, I5, fmaf(E4, I4, fmaf(E3, I3, fmaf(E2, I2, E1 * I1))))));
                float er = hg * SE;
                float ed = hm * SE;

                float ts_ = fmaf(RTOL, fmaxf(fabsf(S[e]),  fabsf(nS)), ATOL);
                float ti_ = fmaf(RTOL, fmaxf(fabsf(I[e]),  fabsf(nI)), ATOL);
                float tr_ = fmaf(RTOL, fmaxf(fabsf(Rr[e]), fabsf(nR)), ATOL);
                float td_ = fmaf(RTOL, fmaxf(fabsf(Dd[e]), fabsf(nD)), ATOL);

                float rs = __fdividef(es, ts_);
                float ri = __fdividef(ei, ti_);
                float rr = __fdividef(er, tr_);
                float rd = __fdividef(ed, td_);
                float enorm2 = 0.25f * (fmaf(rs, rs, ri * ri) + fmaf(rr, rr, rd * rd));

                // fac = clip(0.9 * (enorm2)^-0.1, 0.2, 10); enorm2==0 -> +inf -> 10
                float fac = fminf(fmaxf(0.9f * __powf(enorm2, -0.1f), 0.2f), 10.0f);

                if (!done[e]) {
                    dtv[e] = h * fac;
                    if (enorm2 <= 1.0f) {
                        tcur[e] += h;
                        S[e] = nS; I[e] = nI; Rr[e] = nR; Dd[e] = nD;
                    }
                    if (tcur[e] >= t1 - 1e-6f) done[e] = true;
                }
            }
        }

#pragma unroll
        for (int e = 0; e < NELEM; ++e)
            orow[e][iv + 1] = make_float4(S[e], I[e], Rr[e], Dd[e]);
    }
}

extern "C" void kernel_launch(void* const* d_in, const int* in_sizes, int n_in,
                              void* d_out, int out_size)
{
    const float* x   = (const float*)d_in[0];
    const float* gp  = (const float*)d_in[1];
    const float* pop = (const float*)d_in[2];
    float* out = (float*)d_out;
    int B = in_sizes[2];  // population has B elements

    int threads = 64;
    int nthreads_total = B / NELEM;
    int blocks = (nthreads_total + threads - 1) / threads;
    sird_kernel<<<blocks, threads>>>(x, gp, pop, out, B);
}

// round 6
// speedup vs baseline: 1.2145x; 1.2145x over previous
#include <cuda_runtime.h>

// Tsit5 coefficients (fp32)
#define A21 0.161f
#define A31 (-0.008480655492356989f)
#define A32 0.335480655492357f
#define A41 2.8971530571054935f
#define A42 (-6.359448489975075f)
#define A43 4.3622954328695815f
#define A51 5.325864828439257f
#define A52 (-11.748883564062828f)
#define A53 7.4955393428898365f
#define A54 (-0.09249506636175525f)
#define A61 5.86145544294642f
#define A62 (-12.92096931784711f)
#define A63 8.159367898576159f
#define A64 (-0.071584973281401f)
#define A65 (-0.028269050394068383f)
#define B1 0.09646076681806523f
#define B2 0.01f
#define B3 0.4798896504144996f
#define B4 1.379008574103742f
#define B5 (-3.290069515436081f)
#define B6 2.324710524099774f
#define E1 (-0.001780011052225777f)
#define E2 (-0.0008164344596567469f)
#define E3 0.007880878010261995f
#define E4 (-0.1447110071732629f)
#define E5 0.5823571654525552f
#define E6 (-0.45808210592918697f)
#define E7 0.015151515151515152f

#define ATOL 1e-8f
#define RTOL 1e-4f
#define PRED_LEN 32
#define MAX_STEPS 12

// RHS for S and I only; R' = gamma*I and D' = mu*I are factored out analytically.
#define RHS2(Sv, Iv, dS, dI)                   \
    {                                          \
        float _inf = bN * (Sv) * (Iv);         \
        dS = -_inf;                            \
        dI = fmaf(-gm, (Iv), _inf);            \
    }

__global__ void __launch_bounds__(32) sird_kernel(
    const float* __restrict__ x,          // [B,3] beta,gamma,mu
    const float* __restrict__ gp,         // [B,1]
    const float* __restrict__ population, // [B]
    float* __restrict__ out,              // [B,32,4]
    int B)
{
    int b = blockIdx.x * blockDim.x + threadIdx.x;
    if (b >= B) return;

    const float beta  = x[3 * b + 0];
    const float gamma = x[3 * b + 1];
    const float mu    = x[3 * b + 2];
    const float N     = population[b];
    const float bN    = beta / N;
    const float gm    = gamma + mu;

    float S = gp[b] - 100.0f;
    float I = 100.0f;
    float R = 0.0f;
    float D = 0.0f;

    float4* orow = reinterpret_cast<float4*>(out + (size_t)b * (PRED_LEN * 4));
    orow[0] = make_float4(S, I, R, D);

    float dt = 0.05f;
    const float tstep = 32.0f / 31.0f;

    for (int iv = 0; iv < PRED_LEN - 1; ++iv) {
        const float t1 = (float)(iv + 1) * tstep;
        float t = (float)iv * tstep;

        for (int s = 0; s < MAX_STEPS; ++s) {
            float h = fmaxf(fminf(dt, t1 - t), 1e-9f);

            float k1s, k1i;
            const float I1 = I;
            RHS2(S, I, k1s, k1i);

            float as = fmaf(h, A21 * k1s, S);
            float ai = fmaf(h, A21 * k1i, I);
            const float I2 = ai;
            float k2s, k2i;
            RHS2(as, ai, k2s, k2i);

            as = fmaf(h, fmaf(A32, k2s, A31 * k1s), S);
            ai = fmaf(h, fmaf(A32, k2i, A31 * k1i), I);
            const float I3 = ai;
            float k3s, k3i;
            RHS2(as, ai, k3s, k3i);

            as = fmaf(h, fmaf(A43, k3s, fmaf(A42, k2s, A41 * k1s)), S);
            ai = fmaf(h, fmaf(A43, k3i, fmaf(A42, k2i, A41 * k1i)), I);
            const float I4 = ai;
            float k4s, k4i;
            RHS2(as, ai, k4s, k4i);

            as = fmaf(h, fmaf(A54, k4s, fmaf(A53, k3s, fmaf(A52, k2s, A51 * k1s))), S);
            ai = fmaf(h, fmaf(A54, k4i, fmaf(A53, k3i, fmaf(A52, k2i, A51 * k1i))), I);
            const float I5 = ai;
            float k5s, k5i;
            RHS2(as, ai, k5s, k5i);

            as = fmaf(h, fmaf(A65, k5s, fmaf(A64, k4s, fmaf(A63, k3s, fmaf(A62, k2s, A61 * k1s)))), S);
            ai = fmaf(h, fmaf(A65, k5i, fmaf(A64, k4i, fmaf(A63, k3i, fmaf(A62, k2i, A61 * k1i)))), I);
            const float I6 = ai;
            float k6s, k6i;
            RHS2(as, ai, k6s, k6i);

            float nS = fmaf(h, fmaf(B6, k6s, fmaf(B5, k5s, fmaf(B4, k4s, fmaf(B3, k3s, fmaf(B2, k2s, B1 * k1s))))), S);
            float nI = fmaf(h, fmaf(B6, k6i, fmaf(B5, k5i, fmaf(B4, k4i, fmaf(B3, k3i, fmaf(B2, k2i, B1 * k1i))))), I);
            const float I7 = nI;

            // R/D via factored I-stage sums: k_j^R = gamma*I_j, k_j^D = mu*I_j
            const float SB = fmaf(B6, I6, fmaf(B5, I5, fmaf(B4, I4, fmaf(B3, I3, fmaf(B2, I2, B1 * I1)))));
            const float hg = h * gamma;
            const float hm = h * mu;
            float nR = fmaf(hg, SB, R);
            float nD = fmaf(hm, SB, D);

            float k7s, k7i;
            RHS2(nS, nI, k7s, k7i);

            // error estimates
            float es = h * fmaf(E7, k7s, fmaf(E6, k6s, fmaf(E5, k5s, fmaf(E4, k4s, fmaf(E3, k3s, fmaf(E2, k2s, E1 * k1s))))));
            float ei = h * fmaf(E7, k7i, fmaf(E6, k6i, fmaf(E5, k5i, fmaf(E4, k4i, fmaf(E3, k3i, fmaf(E2, k2i, E1 * k1i))))));
            const float SE = fmaf(E7, I7, fmaf(E6, I6, fmaf(E5, I5, fmaf(E4, I4, fmaf(E3, I3, fmaf(E2, I2, E1 * I1))))));
            float er = hg * SE;
            float ed = hm * SE;

            float ts_ = fmaf(RTOL, fmaxf(fabsf(S), fabsf(nS)), ATOL);
            float ti_ = fmaf(RTOL, fmaxf(fabsf(I), fabsf(nI)), ATOL);
            float tr_ = fmaf(RTOL, fmaxf(fabsf(R), fabsf(nR)), ATOL);
            float td_ = fmaf(RTOL, fmaxf(fabsf(D), fabsf(nD)), ATOL);

            float rs = __fdividef(es, ts_);
            float ri = __fdividef(ei, ti_);
            float rr = __fdividef(er, tr_);
            float rd = __fdividef(ed, td_);
            float enorm2 = 0.25f * (fmaf(rs, rs, ri * ri) + fmaf(rr, rr, rd * rd));

            // fac = clip(0.9 * enorm^-0.2, 0.2, 10);  enorm^-0.2 = (enorm2)^-0.1
            // enorm2 == 0 -> +inf -> clipped to 10 (matches reference clip path).
            float fac = fminf(fmaxf(0.9f * __powf(enorm2, -0.1f), 0.2f), 10.0f);
            dt = h * fac;

            if (enorm2 <= 1.0f) {
                t += h;
                S = nS; I = nI; R = nR; D = nD;
            }
            if (t >= t1 - 1e-6f) break;
        }

        orow[iv + 1] = make_float4(S, I, R, D);
    }
}

extern "C" void kernel_launch(void* const* d_in, const int* in_sizes, int n_in,
                              void* d_out, int out_size)
{
    const float* x   = (const float*)d_in[0];
    const float* gp  = (const float*)d_in[1];
    const float* pop = (const float*)d_in[2];
    float* out = (float*)d_out;
    int B = in_sizes[2];  // population has B elements

    int threads = 32;  // fine-grained blocks: 2048 blocks / 148 SMs -> ~1% imbalance
    int blocks = (B + threads - 1) / threads;
    sird_kernel<<<blocks, threads>>>(x, gp, pop, out, B);
}

// round 8
// speedup vs baseline: 1.2407x; 1.0216x over previous
#include <cuda_runtime.h>

typedef unsigned long long u64;

// ---- packed f32x2 helpers (sm_100+ PTX) ----
__device__ __forceinline__ u64 pk2(float a, float b) {
    u64 r; asm("mov.b64 %0,{%1,%2};" : "=l"(r) : "f"(a), "f"(b)); return r;
}
__device__ __forceinline__ void up2(u64 v, float& a, float& b) {
    asm("mov.b64 {%0,%1},%2;" : "=f"(a), "=f"(b) : "l"(v));
}
__device__ __forceinline__ u64 f2fma(u64 a, u64 b, u64 c) {
    u64 d; asm("fma.rn.f32x2 %0,%1,%2,%3;" : "=l"(d) : "l"(a), "l"(b), "l"(c)); return d;
}
__device__ __forceinline__ u64 f2mul(u64 a, u64 b) {
    u64 d; asm("mul.rn.f32x2 %0,%1,%2;" : "=l"(d) : "l"(a), "l"(b)); return d;
}

// compile-time broadcast of a float into both f32x2 lanes
__host__ __device__ constexpr u64 PKC(float f) {
    unsigned u = __builtin_bit_cast(unsigned, f);
    return ((u64)u << 32) | (u64)u;
}

// Tsit5 coefficients (fp32)
#define A21 0.161f
#define A31 (-0.008480655492356989f)
#define A32 0.335480655492357f
#define A41 2.8971530571054935f
#define A42 (-6.359448489975075f)
#define A43 4.3622954328695815f
#define A51 5.325864828439257f
#define A52 (-11.748883564062828f)
#define A53 7.4955393428898365f
#define A54 (-0.09249506636175525f)
#define A61 5.86145544294642f
#define A62 (-12.92096931784711f)
#define A63 8.159367898576159f
#define A64 (-0.071584973281401f)
#define A65 (-0.028269050394068383f)
#define B1 0.09646076681806523f
#define B2 0.01f
#define B3 0.4798896504144996f
#define B4 1.379008574103742f
#define B5 (-3.290069515436081f)
#define B6 2.324710524099774f
#define E1 (-0.001780011052225777f)
#define E2 (-0.0008164344596567469f)
#define E3 0.007880878010261995f
#define E4 (-0.1447110071732629f)
#define E5 0.5823571654525552f
#define E6 (-0.45808210592918697f)
#define E7 0.015151515151515152f

#define ATOL 1e-8f
#define RTOL 1e-4f
#define PRED_LEN 32
#define MAX_STEPS 12

// RHS producing packed k = (dS, dI). All negations folded into operand signs:
// infn = (-bN*S)*I = -inf; dS = infn; dI = inf - gm*I = fmaf(-gm, I, -infn).
#define PRHS(Sv, Iv, kout)                                 \
    {                                                      \
        float _m   = nbN * (Sv);                           \
        float _infn = _m * (Iv);                           \
        kout = pk2(_infn, fmaf(ngm, (Iv), -_infn));        \
    }

__global__ void __launch_bounds__(32) sird_kernel(
    const float* __restrict__ x,          // [B,3] beta,gamma,mu
    const float* __restrict__ gp,         // [B,1]
    const float* __restrict__ population, // [B]
    float* __restrict__ out,              // [B,32,4]
    int B)
{
    int b = blockIdx.x * blockDim.x + threadIdx.x;
    if (b >= B) return;

    const float beta  = x[3 * b + 0];
    const float gamma = x[3 * b + 1];
    const float mu    = x[3 * b + 2];
    const float N     = population[b];
    const float bN    = beta / N;
    const float nbN   = -bN;
    const float gm    = gamma + mu;
    const float ngm   = -gm;

    float S = gp[b] - 100.0f;
    float I = 100.0f;
    float R = 0.0f;
    float D = 0.0f;

    float4* orow = reinterpret_cast<float4*>(out + (size_t)b * (PRED_LEN * 4));
    orow[0] = make_float4(S, I, R, D);

    float dt = 0.05f;
    const float tstep = 32.0f / 31.0f;

    for (int iv = 0; iv < PRED_LEN - 1; ++iv) {
        const float t1 = (float)(iv + 1) * tstep;
        float t = (float)iv * tstep;

        for (int s = 0; s < MAX_STEPS; ++s) {
            float h = fmaxf(fminf(dt, t1 - t), 1e-9f);
            u64 h2 = pk2(h, h);
            u64 y2 = pk2(S, I);

            float as, ai;
            const float I1 = I;
            u64 k1;
            PRHS(S, I, k1);

            u64 a2 = f2fma(h2, f2mul(PKC(A21), k1), y2);
            up2(a2, as, ai);
            const float I2 = ai;
            u64 k2; PRHS(as, ai, k2);

            a2 = f2fma(h2, f2fma(PKC(A32), k2, f2mul(PKC(A31), k1)), y2);
            up2(a2, as, ai);
            const float I3 = ai;
            u64 k3; PRHS(as, ai, k3);

            a2 = f2fma(h2, f2fma(PKC(A43), k3, f2fma(PKC(A42), k2, f2mul(PKC(A41), k1))), y2);
            up2(a2, as, ai);
            const float I4 = ai;
            u64 k4; PRHS(as, ai, k4);

            a2 = f2fma(h2, f2fma(PKC(A54), k4, f2fma(PKC(A53), k3, f2fma(PKC(A52), k2, f2mul(PKC(A51), k1)))), y2);
            up2(a2, as, ai);
            const float I5 = ai;
            u64 k5; PRHS(as, ai, k5);

            a2 = f2fma(h2, f2fma(PKC(A65), k5, f2fma(PKC(A64), k4, f2fma(PKC(A63), k3, f2fma(PKC(A62), k2, f2mul(PKC(A61), k1))))), y2);
            up2(a2, as, ai);
            const float I6 = ai;
            u64 k6; PRHS(as, ai, k6);

            u64 ny2 = f2fma(h2,
                f2fma(PKC(B6), k6, f2fma(PKC(B5), k5, f2fma(PKC(B4), k4,
                    f2fma(PKC(B3), k3, f2fma(PKC(B2), k2, f2mul(PKC(B1), k1)))))), y2);
            float nS, nI;
            up2(ny2, nS, nI);
            const float I7 = nI;

            // R/D via factored I-stage sums: k_j^R = gamma*I_j, k_j^D = mu*I_j
            const float SB = fmaf(B6, I6, fmaf(B5, I5, fmaf(B4, I4, fmaf(B3, I3, fmaf(B2, I2, B1 * I1)))));
            const float hg = h * gamma;
            const float hm = h * mu;
            float nR = fmaf(hg, SB, R);
            float nD = fmaf(hm, SB, D);

            u64 k7; PRHS(nS, nI, k7);

            // packed error estimate for (S, I)
            u64 e2 = f2mul(h2,
                f2fma(PKC(E7), k7, f2fma(PKC(E6), k6, f2fma(PKC(E5), k5,
                    f2fma(PKC(E4), k4, f2fma(PKC(E3), k3, f2fma(PKC(E2), k2, f2mul(PKC(E1), k1))))))));
            float es, ei;
            up2(e2, es, ei);

            const float SE = fmaf(E7, I7, fmaf(E6, I6, fmaf(E5, I5, fmaf(E4, I4, fmaf(E3, I3, fmaf(E2, I2, E1 * I1))))));
            float er = hg * SE;
            float ed = hm * SE;

            float ts_ = fmaf(RTOL, fmaxf(fabsf(S), fabsf(nS)), ATOL);
            float ti_ = fmaf(RTOL, fmaxf(fabsf(I), fabsf(nI)), ATOL);
            float tr_ = fmaf(RTOL, fmaxf(fabsf(R), fabsf(nR)), ATOL);
            float td_ = fmaf(RTOL, fmaxf(fabsf(D), fabsf(nD)), ATOL);

            float rs = __fdividef(es, ts_);
            float ri = __fdividef(ei, ti_);
            float rr = __fdividef(er, tr_);
            float rd = __fdividef(ed, td_);
            float enorm2 = 0.25f * (fmaf(rs, rs, ri * ri) + fmaf(rr, rr, rd * rd));

            // fac = clip(0.9 * enorm^-0.2, 0.2, 10);  enorm^-0.2 = (enorm2)^-0.1
            // enorm2 == 0 -> +inf -> clipped to 10 (matches reference clip path).
            float fac = fminf(fmaxf(0.9f * __powf(enorm2, -0.1f), 0.2f), 10.0f);
            dt = h * fac;

            if (enorm2 <= 1.0f) {
                t += h;
                S = nS; I = nI; R = nR; D = nD;
            }
            if (t >= t1 - 1e-6f) break;
        }

        orow[iv + 1] = make_float4(S, I, R, D);
    }
}

extern "C" void kernel_launch(void* const* d_in, const int* in_sizes, int n_in,
                              void* d_out, int out_size)
{
    const float* x   = (const float*)d_in[0];
    const float* gp  = (const float*)d_in[1];
    const float* pop = (const float*)d_in[2];
    float* out = (float*)d_out;
    int B = in_sizes[2];  // population has B elements

    int threads = 32;
    int blocks = (B + threads - 1) / threads;
    sird_kernel<<<blocks, threads>>>(x, gp, pop, out, B);
}